// round 7
// baseline (speedup 1.0000x reference)
#include <cuda_runtime.h>

// Problem constants (fixed by the reference): B=2, C=DIMS=64, H=16, W=64,
// HEADS=64 -> per-head channels = 1, S = H*W = 1024.
#define SLEN 1024
#define CH   64
#define NB   2
#define NTOK (NB * CH * SLEN)   // 131072, layout index = (b*64+c)*1024 + s

#define MNODES 32               // Chebyshev nodes / coefficients per head

// log2(e) / sqrt(DIMS) = 1.4426950408889634 / 8
#define K_PRESCALE 0.18033688011112043f

// Scratch (allocation-free rule: __device__ globals).
// g_kv is viewed as float4* in kernels A and B -> force 16B alignment.
__device__ float  g_q[NTOK];
__device__ __align__(16) float2 g_kv[NTOK];   // (k * K_PRESCALE, v) per token
__device__ float  g_o[NTOK];

__device__ __forceinline__ float ex2f(float x) {
    float r;
    asm("ex2.approx.f32 %0, %1;" : "=f"(r) : "f"(x));
    return r;
}

// ---- packed fp32x2 helpers (FFMA2: Blackwell-only, PTX-only pattern) ----
typedef unsigned long long u64;

__device__ __forceinline__ void fma2(u64& d, u64 a, u64 b) {
    asm("fma.rn.f32x2 %0, %1, %2, %0;" : "+l"(d) : "l"(a), "l"(b));
}
__device__ __forceinline__ u64 pack2(float lo, float hi) {
    u64 r; asm("mov.b64 %0, {%1, %2};" : "=l"(r) : "f"(lo), "f"(hi)); return r;
}
__device__ __forceinline__ u64 bcast2(float v) {
    u64 r; asm("mov.b64 %0, {%1, %1};" : "=l"(r) : "f"(v)); return r;
}
__device__ __forceinline__ void unpack2(u64 v, float& lo, float& hi) {
    asm("mov.b64 {%0, %1}, %2;" : "=f"(lo), "=f"(hi) : "l"(v));
}

union F4 { float4 v; float f[4]; };

// ---------------------------------------------------------------------------
// Kernel A: QKV projections (1x1 conv == 64x64 channel-mix GEMM).
// Register-blocked: each thread computes 2 oc x 4 s outputs for all 3
// projections (24 accum floats as 12 f32x2 pairs). Loads are all LDG.128:
// 64 x-loads + 96 warp-uniform W-loads per thread for 1536 FMAs
// (vs 256 scalar LDG per 192 FMAs in round 4 -> ~10x fewer load
// instructions; round-4 ncu showed issue=16.5% with ALL pipes idle, i.e.
// pure LSU-issue/latency bound).
// Grid: 128 CTAs x 128 threads = (b, oc-pair, s-halves).
// ---------------------------------------------------------------------------
__global__ void __launch_bounds__(128) qkv_kernel(
        const float* __restrict__ x,
        const float* __restrict__ Wq, const float* __restrict__ bq,
        const float* __restrict__ Wk, const float* __restrict__ bk,
        const float* __restrict__ Wv, const float* __restrict__ bv) {
    const int tid  = threadIdx.x;
    const int cta  = blockIdx.x;
    const int b    = cta >> 6;              // 0..1
    const int ocp  = (cta >> 1) & 31;       // oc pair index
    const int sblk = cta & 1;               // s half
    const int oc0  = ocp * 2;
    const int oc1  = oc0 + 1;
    const int s0   = sblk * 512 + tid * 4;  // 4 consecutive s per thread

    const float4* x4  = reinterpret_cast<const float4*>(x) + b * 16384 + (s0 >> 2);
    const float4* wq0 = reinterpret_cast<const float4*>(Wq + oc0 * CH);
    const float4* wq1 = reinterpret_cast<const float4*>(Wq + oc1 * CH);
    const float4* wk0 = reinterpret_cast<const float4*>(Wk + oc0 * CH);
    const float4* wk1 = reinterpret_cast<const float4*>(Wk + oc1 * CH);
    const float4* wv0 = reinterpret_cast<const float4*>(Wv + oc0 * CH);
    const float4* wv1 = reinterpret_cast<const float4*>(Wv + oc1 * CH);

    // acc[mat][oc][pair]: mat 0=q,1=k,2=v; pair 0=(s0,s1), 1=(s2,s3)
    u64 acc[3][2][2];
    {
        float bqs0 = __ldg(bq + oc0), bqs1 = __ldg(bq + oc1);
        float bks0 = __ldg(bk + oc0), bks1 = __ldg(bk + oc1);
        float bvs0 = __ldg(bv + oc0), bvs1 = __ldg(bv + oc1);
        acc[0][0][0] = acc[0][0][1] = bcast2(bqs0);
        acc[0][1][0] = acc[0][1][1] = bcast2(bqs1);
        acc[1][0][0] = acc[1][0][1] = bcast2(bks0);
        acc[1][1][0] = acc[1][1][1] = bcast2(bks1);
        acc[2][0][0] = acc[2][0][1] = bcast2(bvs0);
        acc[2][1][0] = acc[2][1][1] = bcast2(bvs1);
    }

    #pragma unroll 4
    for (int c4 = 0; c4 < CH / 4; c4++) {
        F4 q0, q1, k0, k1, v0, v1;
        q0.v = __ldg(wq0 + c4); q1.v = __ldg(wq1 + c4);
        k0.v = __ldg(wk0 + c4); k1.v = __ldg(wk1 + c4);
        v0.v = __ldg(wv0 + c4); v1.v = __ldg(wv1 + c4);
        #pragma unroll
        for (int j = 0; j < 4; j++) {
            float4 xv = __ldg(x4 + (c4 * 4 + j) * 256);   // x[b, c, s0..s0+3]
            u64 xlo = pack2(xv.x, xv.y);
            u64 xhi = pack2(xv.z, xv.w);
            u64 w;
            w = bcast2(q0.f[j]); fma2(acc[0][0][0], xlo, w); fma2(acc[0][0][1], xhi, w);
            w = bcast2(q1.f[j]); fma2(acc[0][1][0], xlo, w); fma2(acc[0][1][1], xhi, w);
            w = bcast2(k0.f[j]); fma2(acc[1][0][0], xlo, w); fma2(acc[1][0][1], xhi, w);
            w = bcast2(k1.f[j]); fma2(acc[1][1][0], xlo, w); fma2(acc[1][1][1], xhi, w);
            w = bcast2(v0.f[j]); fma2(acc[2][0][0], xlo, w); fma2(acc[2][0][1], xhi, w);
            w = bcast2(v1.f[j]); fma2(acc[2][1][0], xlo, w); fma2(acc[2][1][1], xhi, w);
        }
    }

    // Write back: g_q as float4, g_kv as interleaved (k*KP, v) float2 pairs.
    #pragma unroll
    for (int o = 0; o < 2; o++) {
        const int oc = oc0 + o;
        const int base = (b * CH + oc) * SLEN + s0;
        float qa, qb2, qc, qd, ka, kb, kc, kd, va, vb, vc, vd;
        unpack2(acc[0][o][0], qa, qb2); unpack2(acc[0][o][1], qc, qd);
        unpack2(acc[1][o][0], ka, kb);  unpack2(acc[1][o][1], kc, kd);
        unpack2(acc[2][o][0], va, vb);  unpack2(acc[2][o][1], vc, vd);
        *reinterpret_cast<float4*>(g_q + base) = make_float4(qa, qb2, qc, qd);
        float4* kv4 = reinterpret_cast<float4*>(g_kv + base);
        kv4[0] = make_float4(ka * K_PRESCALE, va, kb * K_PRESCALE, vb);
        kv4[1] = make_float4(kc * K_PRESCALE, vc, kd * K_PRESCALE, vd);
    }
}

// ---------------------------------------------------------------------------
// Kernel B: Chebyshev-interpolated rank-1 attention (verified: rel_err 2e-7).
// Per head: o(a) = N(a)/D(a), N(a)=sum_t v_t 2^{a k'_t}, D(a)=sum_t 2^{a k'_t},
// queried at a = q_s. 32-node Chebyshev interpolant on [min q, max q]
// (32x fewer exps than direct eval), then Clenshaw per query.
// One CTA of 1024 threads per head; lane = node, warp = 32-token t-chunk.
// ---------------------------------------------------------------------------
__global__ void __launch_bounds__(1024, 1) attn_cheb_kernel() {
    __shared__ float sk[SLEN];            // k' (prescaled)
    __shared__ float sv[SLEN];            // v
    __shared__ float pN[32 * 33];         // per-warp node partials (padded)
    __shared__ float pD[32 * 33];
    __shared__ float wlo[32], whi[32];    // per-warp q min/max
    __shared__ float nodeN[MNODES], nodeD[MNODES];
    __shared__ float cN[MNODES], cD[MNODES];
    __shared__ float s_mid, s_half;

    const int head = blockIdx.x;
    const int tid  = threadIdx.x;
    const int w    = tid >> 5;
    const int lane = tid & 31;

    // --- Stage k', v; fetch own query scalar ---
    float2 kv = g_kv[head * SLEN + tid];
    sk[tid] = kv.x;
    sv[tid] = kv.y;
    const float myq = g_q[head * SLEN + tid];

    // --- Block min/max of q (defines the interpolation interval) ---
    float lo = myq, hi = myq;
    #pragma unroll
    for (int off = 16; off > 0; off >>= 1) {
        lo = fminf(lo, __shfl_down_sync(0xffffffffu, lo, off));
        hi = fmaxf(hi, __shfl_down_sync(0xffffffffu, hi, off));
    }
    if (lane == 0) { wlo[w] = lo; whi[w] = hi; }
    __syncthreads();
    if (w == 0) {
        lo = wlo[lane]; hi = whi[lane];
        #pragma unroll
        for (int off = 16; off > 0; off >>= 1) {
            lo = fminf(lo, __shfl_down_sync(0xffffffffu, lo, off));
            hi = fmaxf(hi, __shfl_down_sync(0xffffffffu, hi, off));
        }
        if (lane == 0) {
            s_mid  = 0.5f * (lo + hi);
            s_half = fmaxf(0.5f * (hi - lo), 1e-20f);  // degenerate-range guard
        }
    }
    __syncthreads();
    const float mid = s_mid, half = s_half;

    // --- Node sums: lane = node j, warp = t-chunk [w*32, w*32+32) ---
    const float aj = fmaf(half, cospif((lane + 0.5f) * (1.0f / 32.0f)), mid);
    float n = 0.f, d = 0.f;
    const int t0 = w * 32;
    #pragma unroll 8
    for (int i = 0; i < 32; i++) {
        float kk = sk[t0 + i];            // warp-uniform -> LDS broadcast
        float vv = sv[t0 + i];
        float e = ex2f(aj * kk);
        d += e;
        n = fmaf(e, vv, n);
    }
    pN[w * 33 + lane] = n;
    pD[w * 33 + lane] = d;
    __syncthreads();

    // --- Cross-warp reduce: warp j sums the 32 partials of node j ---
    {
        float nn = pN[lane * 33 + w];     // padded stride -> conflict-free
        float dd = pD[lane * 33 + w];
        #pragma unroll
        for (int off = 16; off > 0; off >>= 1) {
            nn += __shfl_down_sync(0xffffffffu, nn, off);
            dd += __shfl_down_sync(0xffffffffu, dd, off);
        }
        if (lane == 0) { nodeN[w] = nn; nodeD[w] = dd; }
    }
    __syncthreads();

    // --- DCT-II: c_i = (2/m) sum_j f_j cos(pi i (j+0.5)/m); warp0->N, warp1->D ---
    if (w < 2) {
        const float* f = (w == 0) ? nodeN : nodeD;
        float c = 0.f;
        for (int j = 0; j < MNODES; j++)
            c = fmaf(f[j], cospif((float)lane * (j + 0.5f) * (1.0f / 32.0f)), c);
        c *= (2.0f / MNODES);
        if (w == 0) cN[lane] = c; else cD[lane] = c;
    }
    __syncthreads();

    // --- Clenshaw evaluation at x = (q_s - mid)/half for N and D jointly ---
    // p(x) = c0/2 + sum_{i>=1} c_i T_i(x);  result = x*b1 - b2 + c0/2
    const float xq = (myq - mid) / half;
    const float x2 = 2.0f * xq;
    float bn1 = 0.f, bn2 = 0.f, bd1 = 0.f, bd2 = 0.f;
    for (int i = MNODES - 1; i >= 1; i--) {
        float tn = fmaf(x2, bn1, cN[i] - bn2);
        float td = fmaf(x2, bd1, cD[i] - bd2);
        bn2 = bn1; bn1 = tn;
        bd2 = bd1; bd1 = td;
    }
    const float Nv = fmaf(xq, bn1, 0.5f * cN[0] - bn2);
    const float Dv = fmaf(xq, bd1, 0.5f * cD[0] - bd2);

    g_o[head * SLEN + tid] = Nv / Dv;
}

// ---------------------------------------------------------------------------
// Kernel C: output projection + residual, same register blocking as qkv.
//   out[b,oc,s] = x[b,oc,s] + bo[oc] + sum_g Wo[oc,g] * o[b,g,s]
// Each thread: 2 oc x 4 s outputs; all loads LDG.128.
// ---------------------------------------------------------------------------
__global__ void __launch_bounds__(128) out_kernel(
        const float* __restrict__ x,
        const float* __restrict__ Wo, const float* __restrict__ bo,
        float* __restrict__ out) {
    const int tid  = threadIdx.x;
    const int cta  = blockIdx.x;
    const int b    = cta >> 6;
    const int ocp  = (cta >> 1) & 31;
    const int sblk = cta & 1;
    const int oc0  = ocp * 2;
    const int oc1  = oc0 + 1;
    const int s0   = sblk * 512 + tid * 4;

    const float4* o4 = reinterpret_cast<const float4*>(g_o) + b * 16384 + (s0 >> 2);
    const float4* w0 = reinterpret_cast<const float4*>(Wo + oc0 * CH);
    const float4* w1 = reinterpret_cast<const float4*>(Wo + oc1 * CH);

    u64 acc[2][2];
    acc[0][0] = acc[0][1] = bcast2(__ldg(bo + oc0));
    acc[1][0] = acc[1][1] = bcast2(__ldg(bo + oc1));

    #pragma unroll 4
    for (int g4 = 0; g4 < CH / 4; g4++) {
        F4 a0, a1;
        a0.v = __ldg(w0 + g4);
        a1.v = __ldg(w1 + g4);
        #pragma unroll
        for (int j = 0; j < 4; j++) {
            float4 ov = __ldg(o4 + (g4 * 4 + j) * 256);
            u64 olo = pack2(ov.x, ov.y);
            u64 ohi = pack2(ov.z, ov.w);
            u64 w;
            w = bcast2(a0.f[j]); fma2(acc[0][0], olo, w); fma2(acc[0][1], ohi, w);
            w = bcast2(a1.f[j]); fma2(acc[1][0], olo, w); fma2(acc[1][1], ohi, w);
        }
    }

    #pragma unroll
    for (int o = 0; o < 2; o++) {
        const int base = (b * CH + (oc0 + o)) * SLEN + s0;
        float4 xv = __ldg(reinterpret_cast<const float4*>(x + base));
        float r0, r1, r2, r3;
        unpack2(acc[o][0], r0, r1);
        unpack2(acc[o][1], r2, r3);
        *reinterpret_cast<float4*>(out + base) =
            make_float4(xv.x + r0, xv.y + r1, xv.z + r2, xv.w + r3);
    }
}

// ---------------------------------------------------------------------------
extern "C" void kernel_launch(void* const* d_in, const int* in_sizes, int n_in,
                              void* d_out, int out_size) {
    const float* x  = (const float*)d_in[0];
    const float* Wq = (const float*)d_in[1];
    const float* bq = (const float*)d_in[2];
    const float* Wk = (const float*)d_in[3];
    const float* bk = (const float*)d_in[4];
    const float* Wv = (const float*)d_in[5];
    const float* bv = (const float*)d_in[6];
    const float* Wo = (const float*)d_in[7];
    const float* bo = (const float*)d_in[8];
    float* out = (float*)d_out;

    qkv_kernel<<<128, 128>>>(x, Wq, bq, Wk, bk, Wv, bv);
    attn_cheb_kernel<<<NB * CH, 1024>>>();
    out_kernel<<<128, 128>>>(x, Wo, bo, out);
}